// round 7
// baseline (speedup 1.0000x reference)
#include <cuda_runtime.h>
#include <cstdint>

// Problem constants
#define Bn  128
#define Tn  512
#define In  128
#define Hn  512
#define NCn 100
#define Vn  101   // NC+1 token values

// Recurrent kernel tiling
#define GRID_R 128          // 8 row-tiles (16 batches) x 16 col-tiles (32 h-units)
#define THR_R  512          // 16 warps: 16-way K-split for latency hiding
#define AST_STRIDE 16       // exact stride (no pad); Cold re-read moved to L2 prefetch
#define WS_FLOATS (512*64)             // B tile: Wpack[:, n0:n0+64], resident all steps (128KB)
#define AST_FLOATS (512*AST_STRIDE)    // A tile transposed: AsT[k][r] (32KB)
#define PS_FLOATS (16*16*64)           // per-warp partials, 16 slots (64KB)
#define SMEM_R_BYTES ((WS_FLOATS + AST_FLOATS + PS_FLOATS) * 4)   // 229376 B

typedef unsigned long long ull;

// packed dual-fp32 ops (sm_100+)
#define FMA2(accv, av, bv) \
    asm("fma.rn.f32x2 %0, %1, %2, %0;" : "+l"(accv) : "l"(av), "l"(bv))
#define ADD2(accv, bv) \
    asm("add.rn.f32x2 %0, %0, %1;" : "+l"(accv) : "l"(bv))
#define PACK_DUP(dst, s) \
    asm("mov.b64 %0, {%1, %1};" : "=l"(dst) : "f"(s))

// ---------------- device-global scratch (no allocations allowed) ----------------
__device__ float d_gtab[Vn * 4 * Hn];     // [tok][gate f,i,o,sig(c)][h]
__device__ float d_Wpack[Hn * 2 * Hn];    // [k][2h+g] g=0:f g=1:i  (512 x 1024)
__device__ float d_Cbuf[2][Bn * Hn];      // double-buffered cell state
__device__ float d_Hf[Bn * Hn];           // final hidden
__device__ unsigned int d_bar;            // monotonic grid barrier counter

__device__ __forceinline__ float sigf(float x) { return 1.0f / (1.0f + expf(-x)); }

// ---------------- init: zero C0, reset barrier ----------------
__global__ void k_init() {
    int i = blockIdx.x * blockDim.x + threadIdx.x;
    if (i < Bn * Hn) d_Cbuf[0][i] = 0.0f;
    if (i == 0) d_bar = 0u;
}

// ---------------- token gate table: gtab[v] = emb[v] @ [Wfx Wix Wox Wcx] + b ----------------
__global__ void k_gtab(const float* __restrict__ emb,
                       const float* __restrict__ Wfx, const float* __restrict__ bf,
                       const float* __restrict__ Wix, const float* __restrict__ bi,
                       const float* __restrict__ Wox, const float* __restrict__ bo,
                       const float* __restrict__ Wcx, const float* __restrict__ bc) {
    __shared__ float es[In];
    int v = blockIdx.x;
    int tid = threadIdx.x;                // 256
    if (tid < In) es[tid] = emb[v * In + tid];
    __syncthreads();
    for (int h = tid; h < Hn; h += 256) {
        float af = bf[h], ai = bi[h], ao = bo[h], ac = bc[h];
        #pragma unroll 4
        for (int k = 0; k < In; k++) {
            float e = es[k];
            af = fmaf(e, Wfx[k * Hn + h], af);
            ai = fmaf(e, Wix[k * Hn + h], ai);
            ao = fmaf(e, Wox[k * Hn + h], ao);
            ac = fmaf(e, Wcx[k * Hn + h], ac);
        }
        d_gtab[v * 2048 + h]        = af;
        d_gtab[v * 2048 + 512 + h]  = ai;
        d_gtab[v * 2048 + 1024 + h] = ao;
        d_gtab[v * 2048 + 1536 + h] = sigf(ac);   // c_tilde has no recurrent term: pre-sigmoid
    }
}

// ---------------- pack Wfc/Wic interleaved by output column ----------------
__global__ void k_wpack(const float* __restrict__ Wfc, const float* __restrict__ Wic) {
    int i = blockIdx.x * blockDim.x + threadIdx.x;   // over H*H
    if (i < Hn * Hn) {
        int k = i / Hn, h = i % Hn;
        d_Wpack[k * 1024 + 2 * h]     = Wfc[i];
        d_Wpack[k * 1024 + 2 * h + 1] = Wic[i];
    }
}

// ---------------- persistent recurrent kernel ----------------
__global__ void __launch_bounds__(THR_R, 1) k_recur(const int* __restrict__ xIdx) {
    extern __shared__ float sm[];
    float* Ws  = sm;                        // [512][64]
    float* AsT = sm + WS_FLOATS;            // [512][16]  transposed C tile
    float* Ps  = AsT + AST_FLOATS;          // [16][16][64]

    const int tid = threadIdx.x;
    const int bx  = blockIdx.x;
    const int rb  = bx >> 4;              // 0..7  row tile (16 batches)
    const int cb  = bx & 15;              // 0..15 col tile (32 h-units)
    const int b0  = rb * 16;
    const int u0  = cb * 32;
    const int n0  = cb * 64;

    // Stage resident B tile (Wpack columns n0..n0+63) once
    for (int li = tid; li < 512 * 16; li += THR_R) {
        int k  = li >> 4;
        int c4 = (li & 15) << 2;
        float4 v = *(const float4*)(d_Wpack + k * 1024 + n0 + c4);
        *(float4*)(Ws + k * 64 + c4) = v;
    }
    __syncthreads();

    const int wid  = tid >> 5;            // 0..15
    const int lane = tid & 31;
    const int tr   = lane & 3;            // row group: rows 4*tr+j
    const int tc   = lane >> 2;           // col group: cols 8*tc+c
    const int ks   = wid * 32;            // K-slice per warp (32 kk each)

    // epilogue: one (batch,row r, h-unit u) per thread
    const int er  = tid >> 5;             // 0..15
    const int eu  = tid & 31;             // 0..31
    const int ehg = u0 + eu;
    const int eb  = b0 + er;

    #pragma unroll 1
    for (int t = 0; t < Tn; t++) {
        const float* Csrc = d_Cbuf[t & 1];

        // ---- prefetch step-t token, gate-table values, and Cold (independent of staging) ----
        int   tok  = xIdx[eb * Tn + t];
        float gf0  = d_gtab[tok * 2048 + ehg];
        float gi0  = d_gtab[tok * 2048 + 512 + ehg];
        float ct0  = d_gtab[tok * 2048 + 1536 + ehg];
        float Cold = __ldcg(&Csrc[eb * Hn + ehg]);

        // ---- stage A tile TRANSPOSED: AsT[k][r] = C_t[b0+r][k] ----
        #pragma unroll
        for (int it = 0; it < 4; it++) {
            int li = tid + it * THR_R;    // 0..2047
            int r  = li & 15;
            int kq = li >> 4;             // 0..127 (k4 = 4*kq)
            float4 v = __ldcg((const float4*)(Csrc + (b0 + r) * Hn + kq * 4));
            float* dst = AsT + (kq * 4) * AST_STRIDE + r;
            dst[0]              = v.x;
            dst[AST_STRIDE]     = v.y;
            dst[2 * AST_STRIDE] = v.z;
            dst[3 * AST_STRIDE] = v.w;
        }
        __syncthreads();

        // ---- GEMM: each warp covers 16x64 outputs over its 32-kk K-slice (packed f32x2) ----
        ull acc[4][4];
        #pragma unroll
        for (int j = 0; j < 4; j++)
            #pragma unroll
            for (int p = 0; p < 4; p++) acc[j][p] = 0ull;

        const float* Ap = AsT + ks * AST_STRIDE + tr * 4;
        const float* Bp = Ws + ks * 64 + tc * 8;
        #pragma unroll 8
        for (int kk = 0; kk < 32; kk++) {
            float4 a4 = *(const float4*)(Ap + kk * AST_STRIDE);
            ulonglong2 b01 = *(const ulonglong2*)(Bp + kk * 64);
            ulonglong2 b23 = *(const ulonglong2*)(Bp + kk * 64 + 4);
            ull ad;
            PACK_DUP(ad, a4.x);
            FMA2(acc[0][0], ad, b01.x); FMA2(acc[0][1], ad, b01.y);
            FMA2(acc[0][2], ad, b23.x); FMA2(acc[0][3], ad, b23.y);
            PACK_DUP(ad, a4.y);
            FMA2(acc[1][0], ad, b01.x); FMA2(acc[1][1], ad, b01.y);
            FMA2(acc[1][2], ad, b23.x); FMA2(acc[1][3], ad, b23.y);
            PACK_DUP(ad, a4.z);
            FMA2(acc[2][0], ad, b01.x); FMA2(acc[2][1], ad, b01.y);
            FMA2(acc[2][2], ad, b23.x); FMA2(acc[2][3], ad, b23.y);
            PACK_DUP(ad, a4.w);
            FMA2(acc[3][0], ad, b01.x); FMA2(acc[3][1], ad, b01.y);
            FMA2(acc[3][2], ad, b23.x); FMA2(acc[3][3], ad, b23.y);
        }

        // ---- write per-warp partials ----
        #pragma unroll
        for (int j = 0; j < 4; j++) {
            int r = tr * 4 + j;
            *(ulonglong2*)(Ps + wid * 1024 + r * 64 + tc * 8) =
                make_ulonglong2(acc[j][0], acc[j][1]);
            *(ulonglong2*)(Ps + wid * 1024 + r * 64 + tc * 8 + 4) =
                make_ulonglong2(acc[j][2], acc[j][3]);
        }
        __syncthreads();

        // ---- reduce 16 partials (packed, conflict-free) + gate epilogue + C update ----
        float* Cdst = d_Cbuf[(t + 1) & 1];
        {
            ull s2 = 0ull;
            const ull* pp = (const ull*)(Ps + er * 64 + 2 * eu);
            #pragma unroll
            for (int w = 0; w < 16; w++) {
                ull v = pp[w * 512];          // 512 ull = 1024 floats per warp slot
                ADD2(s2, v);
            }
            float sf = __uint_as_float((unsigned)(s2 & 0xffffffffu));
            float si = __uint_as_float((unsigned)(s2 >> 32));
            float f  = sigf(gf0 + sf);
            float ig = sigf(gi0 + si);
            float Cn = (tok > 0) ? fmaf(Cold, f, ct0 * ig) : 0.0f;
            __stcg(&Cdst[eb * Hn + ehg], Cn);
        }

        // ---- grid barrier (monotonic counter) ----
        __syncthreads();
        if (tid == 0) {
            __threadfence();                       // release C writes
            atomicAdd(&d_bar, 1u);
            unsigned target = (unsigned)(t + 1) * (unsigned)GRID_R;
            while (*((volatile unsigned int*)&d_bar) < target) { __nanosleep(40); }
            __threadfence();                       // acquire
        }
        __syncthreads();
    }
}

// ---------------- final: o gate + h = tanh(C_T)*o ----------------
__global__ void k_final_h(const int* __restrict__ xIdx, const float* __restrict__ Woc) {
    __shared__ float cps[Hn];
    int b = blockIdx.x;
    int tid = threadIdx.x;                         // 128
    const float* Cprev = d_Cbuf[(Tn - 1) & 1];     // C_{T-1}
    const float* Clast = d_Cbuf[Tn & 1];           // C_T
    for (int k = tid; k < Hn; k += 128) cps[k] = Cprev[b * Hn + k];
    __syncthreads();
    int tok = xIdx[b * Tn + (Tn - 1)];
    float acc[4] = {0.f, 0.f, 0.f, 0.f};
    #pragma unroll 4
    for (int k = 0; k < Hn; k++) {
        float c = cps[k];
        const float* wr = Woc + k * Hn + tid;
        acc[0] = fmaf(c, wr[0],   acc[0]);
        acc[1] = fmaf(c, wr[128], acc[1]);
        acc[2] = fmaf(c, wr[256], acc[2]);
        acc[3] = fmaf(c, wr[384], acc[3]);
    }
    #pragma unroll
    for (int m = 0; m < 4; m++) {
        int h = tid + m * 128;
        float o = sigf(d_gtab[tok * 2048 + 1024 + h] + acc[m]);
        d_Hf[b * Hn + h] = tanhf(Clast[b * Hn + h]) * o;
    }
}

// ---------------- final: logits + log_softmax ----------------
__global__ void k_final_p(const float* __restrict__ Wph, const float* __restrict__ bp,
                          float* __restrict__ out) {
    __shared__ float hs[Hn];
    __shared__ float red[128];
    int b = blockIdx.x;
    int tid = threadIdx.x;                         // 128
    for (int k = tid; k < Hn; k += 128) hs[k] = d_Hf[b * Hn + k];
    __syncthreads();
    float p = -INFINITY;
    if (tid < NCn) {
        p = bp[tid];
        #pragma unroll 4
        for (int k = 0; k < Hn; k++) p = fmaf(hs[k], Wph[k * NCn + tid], p);
    }
    red[tid] = p;
    __syncthreads();
    for (int s = 64; s > 0; s >>= 1) {
        if (tid < s) red[tid] = fmaxf(red[tid], red[tid + s]);
        __syncthreads();
    }
    float mx = red[0];
    __syncthreads();
    red[tid] = (tid < NCn) ? expf(p - mx) : 0.0f;
    __syncthreads();
    for (int s = 64; s > 0; s >>= 1) {
        if (tid < s) red[tid] += red[tid + s];
        __syncthreads();
    }
    float lse = mx + logf(red[0]);
    if (tid < NCn) out[b * NCn + tid] = p - lse;
}

// ---------------- launch ----------------
extern "C" void kernel_launch(void* const* d_in, const int* in_sizes, int n_in,
                              void* d_out, int out_size) {
    (void)in_sizes; (void)n_in; (void)out_size;
    const int*   x   = (const int*)  d_in[0];
    const float* emb = (const float*)d_in[1];
    const float* Wfx = (const float*)d_in[2];
    const float* Wfc = (const float*)d_in[3];
    const float* bf  = (const float*)d_in[4];
    const float* Wix = (const float*)d_in[5];
    const float* Wic = (const float*)d_in[6];
    const float* bi  = (const float*)d_in[7];
    const float* Wox = (const float*)d_in[8];
    const float* Woc = (const float*)d_in[9];
    const float* bo  = (const float*)d_in[10];
    const float* Wcx = (const float*)d_in[11];
    const float* bc  = (const float*)d_in[12];
    const float* Wph = (const float*)d_in[13];
    const float* bp  = (const float*)d_in[14];
    float* out = (float*)d_out;

    cudaFuncSetAttribute(k_recur, cudaFuncAttributeMaxDynamicSharedMemorySize, SMEM_R_BYTES);

    k_init<<<(Bn * Hn + 255) / 256, 256>>>();
    k_gtab<<<Vn, 256>>>(emb, Wfx, bf, Wix, bi, Wox, bo, Wcx, bc);
    k_wpack<<<(Hn * Hn + 255) / 256, 256>>>(Wfc, Wic);
    k_recur<<<GRID_R, THR_R, SMEM_R_BYTES>>>(x);
    k_final_h<<<Bn, 128>>>(x, Woc);
    k_final_p<<<Bn, 128>>>(Wph, bp, out);
}

// round 9
// speedup vs baseline: 1.0865x; 1.0865x over previous
#include <cuda_runtime.h>
#include <cstdint>

// Problem constants
#define Bn  128
#define Tn  512
#define In  128
#define Hn  512
#define NCn 100
#define Vn  101   // NC+1 token values

// Recurrent kernel tiling
#define GRID_R 128          // 8 row-tiles (16 batches) x 16 col-tiles (32 h-units)
#define THR_R  512          // 16 warps: 16-way K-split
#define AST_STRIDE 16
#define WS_FLOATS (512*64)             // B tile: Wpack[:, n0:n0+64] (128KB)
#define AST_FLOATS (512*AST_STRIDE)    // A tile transposed: AsT[k][r] (32KB)
#define PS_FLOATS (16*16*64)           // per-warp partials, 16 slots (64KB)
#define SMEM_R_BYTES ((WS_FLOATS + AST_FLOATS + PS_FLOATS) * 4)   // 229376 B

typedef unsigned long long ull;

// packed dual-fp32 ops (sm_100+)
#define FMA2(accv, av, bv) \
    asm("fma.rn.f32x2 %0, %1, %2, %0;" : "+l"(accv) : "l"(av), "l"(bv))
#define ADD2(accv, bv) \
    asm("add.rn.f32x2 %0, %0, %1;" : "+l"(accv) : "l"(bv))
#define PACK_DUP(dst, s) \
    asm("mov.b64 %0, {%1, %1};" : "=l"(dst) : "f"(s))

// ---------------- device-global scratch (no allocations allowed) ----------------
__device__ float d_gtab[Vn * 4 * Hn];     // [tok][gate f,i,o,sig(c)][h]
__device__ float d_Wpack[Hn * 2 * Hn];    // [k][2h+g] g=0:f g=1:i  (512 x 1024)
__device__ float d_Cbuf[2][Bn * Hn];      // double-buffered cell state
__device__ float d_Hf[Bn * Hn];           // final hidden
__device__ unsigned int d_barArr[8 * 32]; // per-row-group monotonic counters (128B apart)

__device__ __forceinline__ float sigf(float x) { return 1.0f / (1.0f + expf(-x)); }

// ---------------- init: zero C0, reset barriers ----------------
__global__ void k_init() {
    int i = blockIdx.x * blockDim.x + threadIdx.x;
    if (i < Bn * Hn) d_Cbuf[0][i] = 0.0f;
    if (i < 8 * 32) d_barArr[i] = 0u;
}

// ---------------- token gate table: gtab[v] = emb[v] @ [Wfx Wix Wox Wcx] + b ----------------
__global__ void k_gtab(const float* __restrict__ emb,
                       const float* __restrict__ Wfx, const float* __restrict__ bf,
                       const float* __restrict__ Wix, const float* __restrict__ bi,
                       const float* __restrict__ Wox, const float* __restrict__ bo,
                       const float* __restrict__ Wcx, const float* __restrict__ bc) {
    __shared__ float es[In];
    int v = blockIdx.x;
    int tid = threadIdx.x;                // 256
    if (tid < In) es[tid] = emb[v * In + tid];
    __syncthreads();
    for (int h = tid; h < Hn; h += 256) {
        float af = bf[h], ai = bi[h], ao = bo[h], ac = bc[h];
        #pragma unroll 4
        for (int k = 0; k < In; k++) {
            float e = es[k];
            af = fmaf(e, Wfx[k * Hn + h], af);
            ai = fmaf(e, Wix[k * Hn + h], ai);
            ao = fmaf(e, Wox[k * Hn + h], ao);
            ac = fmaf(e, Wcx[k * Hn + h], ac);
        }
        d_gtab[v * 2048 + h]        = af;
        d_gtab[v * 2048 + 512 + h]  = ai;
        d_gtab[v * 2048 + 1024 + h] = ao;
        d_gtab[v * 2048 + 1536 + h] = sigf(ac);   // c_tilde has no recurrent term: pre-sigmoid
    }
}

// ---------------- pack Wfc/Wic interleaved by output column ----------------
__global__ void k_wpack(const float* __restrict__ Wfc, const float* __restrict__ Wic) {
    int i = blockIdx.x * blockDim.x + threadIdx.x;   // over H*H
    if (i < Hn * Hn) {
        int k = i / Hn, h = i % Hn;
        d_Wpack[k * 1024 + 2 * h]     = Wfc[i];
        d_Wpack[k * 1024 + 2 * h + 1] = Wic[i];
    }
}

// ---------------- persistent recurrent kernel ----------------
__global__ void __launch_bounds__(THR_R, 1) k_recur(const int* __restrict__ xIdx) {
    extern __shared__ float sm[];
    float* Ws  = sm;                        // [512][64]
    float* AsT = sm + WS_FLOATS;            // [512][16]  transposed C tile
    float* Ps  = AsT + AST_FLOATS;          // [16][16][64]

    const int tid = threadIdx.x;
    const int bx  = blockIdx.x;
    const int rb  = bx >> 4;              // 0..7  row tile (16 batches)
    const int cb  = bx & 15;              // 0..15 col tile (32 h-units)
    const int b0  = rb * 16;
    const int u0  = cb * 32;
    const int n0  = cb * 64;

    // Stage resident B tile (Wpack columns n0..n0+63) once
    for (int li = tid; li < 512 * 16; li += THR_R) {
        int k  = li >> 4;
        int c4 = (li & 15) << 2;
        float4 v = *(const float4*)(d_Wpack + k * 1024 + n0 + c4);
        *(float4*)(Ws + k * 64 + c4) = v;
    }
    __syncthreads();

    const int wid  = tid >> 5;            // 0..15
    const int lane = tid & 31;
    const int tr   = lane & 3;            // row group: rows 4*tr+j
    const int tc   = lane >> 2;           // col group: cols {4tc..4tc+3, 32+4tc..32+4tc+3}
    const int ks   = wid * 32;            // K-slice per warp (32 kk each)

    // per-warp staging indices: lane handles row r2, k-half ch
    const int r2 = lane >> 1;             // 0..15
    const int ch = lane & 1;              // 0/1 -> k offset 0/16

    // epilogue: one (batch row er, h-unit eu) per thread
    const int er  = tid >> 5;             // 0..15
    const int eu  = tid & 31;             // 0..31
    const int ehg = u0 + eu;
    const int eb  = b0 + er;

    unsigned int* barp = &d_barArr[rb * 32];

    #pragma unroll 1
    for (int t = 0; t < Tn; t++) {
        const float* Csrc = d_Cbuf[t & 1];

        // ---- prefetch step-t token, gate-table values, and Cold ----
        int   tok  = xIdx[eb * Tn + t];
        float gf0  = d_gtab[tok * 2048 + ehg];
        float gi0  = d_gtab[tok * 2048 + 512 + ehg];
        float ct0  = d_gtab[tok * 2048 + 1536 + ehg];
        float Cold = __ldcg(&Csrc[eb * Hn + ehg]);

        // ---- warp-local staging of this warp's K-slice: AsT[k][r] = C[b0+r][k] ----
        {
            const float* srcRow = Csrc + (b0 + r2) * Hn + ks + ch * 16;
            #pragma unroll
            for (int j = 0; j < 4; j++) {
                float4 v = __ldcg((const float4*)(srcRow + j * 4));
                float* dst = AsT + (ks + ch * 16 + j * 4) * AST_STRIDE + r2;
                dst[0]              = v.x;
                dst[AST_STRIDE]     = v.y;
                dst[2 * AST_STRIDE] = v.z;
                dst[3 * AST_STRIDE] = v.w;
            }
        }
        __syncwarp();

        // ---- GEMM: warp covers 16x64 outputs over its 32-kk K-slice ----
        // register double-buffered, B layout: cols {4tc..4tc+3} and {32+4tc..+3}
        ull acc[4][4];
        #pragma unroll
        for (int j = 0; j < 4; j++)
            #pragma unroll
            for (int p = 0; p < 4; p++) acc[j][p] = 0ull;

        const float* Ap = AsT + ks * AST_STRIDE + tr * 4;
        const float* Bp = Ws + ks * 64 + tc * 4;

        float4     a_c  = *(const float4*)(Ap);
        ulonglong2 b0_c = *(const ulonglong2*)(Bp);
        ulonglong2 b1_c = *(const ulonglong2*)(Bp + 32);

        #pragma unroll
        for (int kk = 0; kk < 32; kk++) {
            const int kn = (kk + 1) & 31;
            float4     a_n  = *(const float4*)(Ap + kn * AST_STRIDE);
            ulonglong2 b0_n = *(const ulonglong2*)(Bp + kn * 64);
            ulonglong2 b1_n = *(const ulonglong2*)(Bp + kn * 64 + 32);
            ull ad;
            PACK_DUP(ad, a_c.x);
            FMA2(acc[0][0], ad, b0_c.x); FMA2(acc[0][1], ad, b0_c.y);
            FMA2(acc[0][2], ad, b1_c.x); FMA2(acc[0][3], ad, b1_c.y);
            PACK_DUP(ad, a_c.y);
            FMA2(acc[1][0], ad, b0_c.x); FMA2(acc[1][1], ad, b0_c.y);
            FMA2(acc[1][2], ad, b1_c.x); FMA2(acc[1][3], ad, b1_c.y);
            PACK_DUP(ad, a_c.z);
            FMA2(acc[2][0], ad, b0_c.x); FMA2(acc[2][1], ad, b0_c.y);
            FMA2(acc[2][2], ad, b1_c.x); FMA2(acc[2][3], ad, b1_c.y);
            PACK_DUP(ad, a_c.w);
            FMA2(acc[3][0], ad, b0_c.x); FMA2(acc[3][1], ad, b0_c.y);
            FMA2(acc[3][2], ad, b1_c.x); FMA2(acc[3][3], ad, b1_c.y);
            a_c = a_n; b0_c = b0_n; b1_c = b1_n;
        }

        // ---- write per-warp partials (col layout matches Ps linear cols) ----
        #pragma unroll
        for (int j = 0; j < 4; j++) {
            int r = tr * 4 + j;
            *(ulonglong2*)(Ps + wid * 1024 + r * 64 + tc * 4) =
                make_ulonglong2(acc[j][0], acc[j][1]);
            *(ulonglong2*)(Ps + wid * 1024 + r * 64 + 32 + tc * 4) =
                make_ulonglong2(acc[j][2], acc[j][3]);
        }
        __syncthreads();

        // ---- tree-reduce 16 partials + gate epilogue + C update ----
        float* Cdst = d_Cbuf[(t + 1) & 1];
        {
            const ull* pp = (const ull*)Ps + er * 32 + eu;
            ull s0 = 0ull, s1 = 0ull, s2 = 0ull, s3 = 0ull;
            #pragma unroll
            for (int w = 0; w < 16; w += 4) {
                ull v0 = pp[(w + 0) * 512];
                ull v1 = pp[(w + 1) * 512];
                ull v2 = pp[(w + 2) * 512];
                ull v3 = pp[(w + 3) * 512];
                ADD2(s0, v0); ADD2(s1, v1); ADD2(s2, v2); ADD2(s3, v3);
            }
            ADD2(s0, s1); ADD2(s2, s3); ADD2(s0, s2);
            float sf = __uint_as_float((unsigned)(s0 & 0xffffffffu));
            float si = __uint_as_float((unsigned)(s0 >> 32));
            float f  = sigf(gf0 + sf);
            float ig = sigf(gi0 + si);
            float Cn = (tok > 0) ? fmaf(Cold, f, ct0 * ig) : 0.0f;
            __stcg(&Cdst[eb * Hn + ehg], Cn);
        }

        // ---- row-group barrier (16 blocks share this counter) ----
        __syncthreads();
        if (tid == 0) {
            __threadfence();                       // release C writes
            atomicAdd(barp, 1u);
            unsigned target = (unsigned)(t + 1) * 16u;
            while (*((volatile unsigned int*)barp) < target) { __nanosleep(20); }
            __threadfence();                       // acquire
        }
        __syncthreads();
    }
}

// ---------------- final: o gate + h = tanh(C_T)*o ----------------
__global__ void k_final_h(const int* __restrict__ xIdx, const float* __restrict__ Woc) {
    __shared__ float cps[Hn];
    int b = blockIdx.x;
    int tid = threadIdx.x;                         // 128
    const float* Cprev = d_Cbuf[(Tn - 1) & 1];     // C_{T-1}
    const float* Clast = d_Cbuf[Tn & 1];           // C_T
    for (int k = tid; k < Hn; k += 128) cps[k] = Cprev[b * Hn + k];
    __syncthreads();
    int tok = xIdx[b * Tn + (Tn - 1)];
    float acc[4] = {0.f, 0.f, 0.f, 0.f};
    #pragma unroll 4
    for (int k = 0; k < Hn; k++) {
        float c = cps[k];
        const float* wr = Woc + k * Hn + tid;
        acc[0] = fmaf(c, wr[0],   acc[0]);
        acc[1] = fmaf(c, wr[128], acc[1]);
        acc[2] = fmaf(c, wr[256], acc[2]);
        acc[3] = fmaf(c, wr[384], acc[3]);
    }
    #pragma unroll
    for (int m = 0; m < 4; m++) {
        int h = tid + m * 128;
        float o = sigf(d_gtab[tok * 2048 + 1024 + h] + acc[m]);
        d_Hf[b * Hn + h] = tanhf(Clast[b * Hn + h]) * o;
    }
}

// ---------------- final: logits + log_softmax ----------------
__global__ void k_final_p(const float* __restrict__ Wph, const float* __restrict__ bp,
                          float* __restrict__ out) {
    __shared__ float hs[Hn];
    __shared__ float red[128];
    int b = blockIdx.x;
    int tid = threadIdx.x;                         // 128
    for (int k = tid; k < Hn; k += 128) hs[k] = d_Hf[b * Hn + k];
    __syncthreads();
    float p = -INFINITY;
    if (tid < NCn) {
        p = bp[tid];
        #pragma unroll 4
        for (int k = 0; k < Hn; k++) p = fmaf(hs[k], Wph[k * NCn + tid], p);
    }
    red[tid] = p;
    __syncthreads();
    for (int s = 64; s > 0; s >>= 1) {
        if (tid < s) red[tid] = fmaxf(red[tid], red[tid + s]);
        __syncthreads();
    }
    float mx = red[0];
    __syncthreads();
    red[tid] = (tid < NCn) ? expf(p - mx) : 0.0f;
    __syncthreads();
    for (int s = 64; s > 0; s >>= 1) {
        if (tid < s) red[tid] += red[tid + s];
        __syncthreads();
    }
    float lse = mx + logf(red[0]);
    if (tid < NCn) out[b * NCn + tid] = p - lse;
}

// ---------------- launch ----------------
extern "C" void kernel_launch(void* const* d_in, const int* in_sizes, int n_in,
                              void* d_out, int out_size) {
    (void)in_sizes; (void)n_in; (void)out_size;
    const int*   x   = (const int*)  d_in[0];
    const float* emb = (const float*)d_in[1];
    const float* Wfx = (const float*)d_in[2];
    const float* Wfc = (const float*)d_in[3];
    const float* bf  = (const float*)d_in[4];
    const float* Wix = (const float*)d_in[5];
    const float* Wic = (const float*)d_in[6];
    const float* bi  = (const float*)d_in[7];
    const float* Wox = (const float*)d_in[8];
    const float* Woc = (const float*)d_in[9];
    const float* bo  = (const float*)d_in[10];
    const float* Wcx = (const float*)d_in[11];
    const float* bc  = (const float*)d_in[12];
    const float* Wph = (const float*)d_in[13];
    const float* bp  = (const float*)d_in[14];
    float* out = (float*)d_out;

    cudaFuncSetAttribute(k_recur, cudaFuncAttributeMaxDynamicSharedMemorySize, SMEM_R_BYTES);

    k_init<<<(Bn * Hn + 255) / 256, 256>>>();
    k_gtab<<<Vn, 256>>>(emb, Wfx, bf, Wix, bi, Wox, bo, Wcx, bc);
    k_wpack<<<(Hn * Hn + 255) / 256, 256>>>(Wfc, Wic);
    k_recur<<<GRID_R, THR_R, SMEM_R_BYTES>>>(x);
    k_final_h<<<Bn, 128>>>(x, Woc);
    k_final_p<<<Bn, 128>>>(Wph, bp, out);
}